// round 3
// baseline (speedup 1.0000x reference)
#include <cuda_runtime.h>

// Problem constants
#define BB   2
#define SS   2048
#define EE   4096
#define HH   16
#define DD   256
#define RR   64
#define NTOK (BB * SS)       // 4096 tokens
#define NEG_INF (-3.402823466e38f)

// Scratch for layernorm output (64 MB, static device global — no allocation)
__device__ float g_xnorm[(size_t)NTOK * EE];

// ---------------------------------------------------------------------------
// Kernel 1: LayerNorm. One block per token row of 4096.
// ---------------------------------------------------------------------------
__global__ void __launch_bounds__(256) ln_kernel(const float* __restrict__ x,
                                                 const float* __restrict__ lnw,
                                                 const float* __restrict__ lnb) {
    __shared__ float sred[16];
    int row = blockIdx.x;
    const float* xr = x + (size_t)row * EE;
    float* outr = g_xnorm + (size_t)row * EE;
    int t = threadIdx.x;

    float4 vv[4];
    float s = 0.f, ss = 0.f;
#pragma unroll
    for (int u = 0; u < 4; u++) {
        vv[u] = *(const float4*)(xr + u * 1024 + t * 4);
        s  += vv[u].x + vv[u].y + vv[u].z + vv[u].w;
        ss += vv[u].x * vv[u].x + vv[u].y * vv[u].y
            + vv[u].z * vv[u].z + vv[u].w * vv[u].w;
    }
#pragma unroll
    for (int o = 16; o; o >>= 1) {
        s  += __shfl_xor_sync(0xffffffffu, s, o);
        ss += __shfl_xor_sync(0xffffffffu, ss, o);
    }
    if ((t & 31) == 0) { sred[t >> 5] = s; sred[8 + (t >> 5)] = ss; }
    __syncthreads();
    if (t < 8) {
        float a = sred[t], b = sred[8 + t];
#pragma unroll
        for (int o = 4; o; o >>= 1) {
            a += __shfl_xor_sync(0xffu, a, o);
            b += __shfl_xor_sync(0xffu, b, o);
        }
        if (t == 0) { sred[0] = a; sred[8] = b; }
    }
    __syncthreads();
    float mean = sred[0] * (1.0f / EE);
    float var  = sred[8] * (1.0f / EE) - mean * mean;
    float inv  = rsqrtf(var + 1e-5f);

#pragma unroll
    for (int u = 0; u < 4; u++) {
        float4 w = *(const float4*)(lnw + u * 1024 + t * 4);
        float4 b = *(const float4*)(lnb + u * 1024 + t * 4);
        float4 o;
        o.x = (vv[u].x - mean) * inv * w.x + b.x;
        o.y = (vv[u].y - mean) * inv * w.y + b.y;
        o.z = (vv[u].z - mean) * inv * w.z + b.z;
        o.w = (vv[u].w - mean) * inv * w.w + b.w;
        *(float4*)(outr + u * 1024 + t * 4) = o;
    }
}

// ---------------------------------------------------------------------------
// Kernel 2: projection GEMM  C[m,n] = sum_k xnorm[m,k] * W[n,k] + bias[n],
// fused GPT-J RoPE on head-dims < 64, stored transposed to (B,H,S,D).
// 128x128 tile, BK=8, 256 threads, 8x8 microtile.
// ---------------------------------------------------------------------------
__global__ void __launch_bounds__(256) proj_kernel(const float* __restrict__ W,
                                                   const float* __restrict__ bias,
                                                   const float* __restrict__ ep,
                                                   const int* __restrict__ pid,
                                                   float* __restrict__ out) {
    __shared__ float As[8][128];
    __shared__ float Bs[8][128];
    int tid = threadIdx.x;
    int tx = tid & 15, ty = tid >> 4;
    int bm = blockIdx.y * 128, bn = blockIdx.x * 128;
    int lrow = tid >> 1, lc4 = (tid & 1) * 4;

    const float* aptr = g_xnorm + (size_t)(bm + lrow) * EE + lc4;
    const float* wptr = W       + (size_t)(bn + lrow) * EE + lc4;

    float acc[8][8];
#pragma unroll
    for (int i = 0; i < 8; i++)
#pragma unroll
        for (int j = 0; j < 8; j++) acc[i][j] = 0.f;

    for (int kt = 0; kt < EE; kt += 8) {
        float4 av = *(const float4*)(aptr + kt);
        float4 wv = *(const float4*)(wptr + kt);
        __syncthreads();
        As[lc4 + 0][lrow] = av.x; As[lc4 + 1][lrow] = av.y;
        As[lc4 + 2][lrow] = av.z; As[lc4 + 3][lrow] = av.w;
        Bs[lc4 + 0][lrow] = wv.x; Bs[lc4 + 1][lrow] = wv.y;
        Bs[lc4 + 2][lrow] = wv.z; Bs[lc4 + 3][lrow] = wv.w;
        __syncthreads();
#pragma unroll
        for (int k = 0; k < 8; k++) {
            float a[8], b[8];
            *(float4*)&a[0] = *(const float4*)&As[k][ty * 8];
            *(float4*)&a[4] = *(const float4*)&As[k][ty * 8 + 4];
            *(float4*)&b[0] = *(const float4*)&Bs[k][tx * 8];
            *(float4*)&b[4] = *(const float4*)&Bs[k][tx * 8 + 4];
#pragma unroll
            for (int i = 0; i < 8; i++)
#pragma unroll
                for (int j = 0; j < 8; j++)
                    acc[i][j] = fmaf(a[i], b[j], acc[i][j]);
        }
    }

    // Epilogue: bias + RoPE + transposed store.
    int n0 = bn + tx * 8;
    int h  = n0 >> 8;          // head index (n0 within one 256-wide head half)
    int d0 = n0 & 255;         // dim within head, multiple of 8
    float bi[8];
    *(float4*)&bi[0] = *(const float4*)(bias + n0);
    *(float4*)&bi[4] = *(const float4*)(bias + n0 + 4);
    bool rope = (d0 < RR);     // whole 8-wide group inside or outside RoPE region
    int j0 = d0 >> 1;

#pragma unroll
    for (int i = 0; i < 8; i++) {
        int m = bm + ty * 8 + i;
        int b = m >> 11;           // batch (S = 2048)
        int s = m & (SS - 1);
        float r[8];
#pragma unroll
        for (int j = 0; j < 8; j++) r[j] = acc[i][j] + bi[j];
        if (rope) {
            int pos = pid[m];
            const float* epp = ep + (size_t)pos * RR;
#pragma unroll
            for (int p = 0; p < 4; p++) {
                float sv = epp[j0 + p];
                float cv = epp[32 + j0 + p];
                float t0 = r[2 * p], t1 = r[2 * p + 1];
                r[2 * p]     = t0 * cv - t1 * sv;
                r[2 * p + 1] = t1 * cv + t0 * sv;
            }
        }
        float* o = out + (((size_t)(b * HH + h)) * SS + s) * DD + d0;
        *(float4*)o       = make_float4(r[0], r[1], r[2], r[3]);
        *(float4*)(o + 4) = make_float4(r[4], r[5], r[6], r[7]);
    }
}

// ---------------------------------------------------------------------------
// Kernel 3: causal scores GEMM: scores[bh,i,j] = dot(q_i, k_j) / 16.
// Same tiling; fully-masked tiles (j_tile > i_tile) skipped. Upper-triangle
// garbage within diagonal tiles is overwritten by the softmax pass.
// ---------------------------------------------------------------------------
__global__ void __launch_bounds__(256) scores_kernel(const float* __restrict__ Q,
                                                     const float* __restrict__ Kp,
                                                     float* __restrict__ attn) {
    if (blockIdx.x > blockIdx.y) return;   // fully masked tile
    __shared__ float As[8][128];
    __shared__ float Bs[8][128];
    int tid = threadIdx.x;
    int tx = tid & 15, ty = tid >> 4;
    int bh = blockIdx.z;
    int bi0 = blockIdx.y * 128, bj0 = blockIdx.x * 128;
    int lrow = tid >> 1, lc4 = (tid & 1) * 4;

    const float* aptr = Q  + (size_t)bh * SS * DD + (size_t)(bi0 + lrow) * DD + lc4;
    const float* bptr = Kp + (size_t)bh * SS * DD + (size_t)(bj0 + lrow) * DD + lc4;

    float acc[8][8];
#pragma unroll
    for (int i = 0; i < 8; i++)
#pragma unroll
        for (int j = 0; j < 8; j++) acc[i][j] = 0.f;

    for (int kt = 0; kt < DD; kt += 8) {
        float4 av = *(const float4*)(aptr + kt);
        float4 bv = *(const float4*)(bptr + kt);
        __syncthreads();
        As[lc4 + 0][lrow] = av.x; As[lc4 + 1][lrow] = av.y;
        As[lc4 + 2][lrow] = av.z; As[lc4 + 3][lrow] = av.w;
        Bs[lc4 + 0][lrow] = bv.x; Bs[lc4 + 1][lrow] = bv.y;
        Bs[lc4 + 2][lrow] = bv.z; Bs[lc4 + 3][lrow] = bv.w;
        __syncthreads();
#pragma unroll
        for (int k = 0; k < 8; k++) {
            float a[8], b[8];
            *(float4*)&a[0] = *(const float4*)&As[k][ty * 8];
            *(float4*)&a[4] = *(const float4*)&As[k][ty * 8 + 4];
            *(float4*)&b[0] = *(const float4*)&Bs[k][tx * 8];
            *(float4*)&b[4] = *(const float4*)&Bs[k][tx * 8 + 4];
#pragma unroll
            for (int i = 0; i < 8; i++)
#pragma unroll
                for (int j = 0; j < 8; j++)
                    acc[i][j] = fmaf(a[i], b[j], acc[i][j]);
        }
    }

    float* C = attn + (size_t)bh * SS * SS;
    int j0 = bj0 + tx * 8;
#pragma unroll
    for (int i = 0; i < 8; i++) {
        int irow = bi0 + ty * 8 + i;
        float* o = C + (size_t)irow * SS + j0;
        *(float4*)o = make_float4(acc[i][0] * 0.0625f, acc[i][1] * 0.0625f,
                                  acc[i][2] * 0.0625f, acc[i][3] * 0.0625f);
        *(float4*)(o + 4) = make_float4(acc[i][4] * 0.0625f, acc[i][5] * 0.0625f,
                                        acc[i][6] * 0.0625f, acc[i][7] * 0.0625f);
    }
}

// ---------------------------------------------------------------------------
// Kernel 4: in-place causal softmax. One block per attention row.
// Row data held in registers (8 per thread). Writes zeros above diagonal.
// ---------------------------------------------------------------------------
__global__ void __launch_bounds__(256) softmax_kernel(float* __restrict__ attn) {
    __shared__ float sred[8];
    int r = blockIdx.x;
    int i = r & (SS - 1);
    float* p = attn + (size_t)r * SS;
    int valid = i + 1;
    int t = threadIdx.x;

    float v[8];
    float mx = NEG_INF;
#pragma unroll
    for (int u = 0; u < 8; u++) {
        int j = t + u * 256;
        v[u] = (j < valid) ? p[j] : NEG_INF;
        mx = fmaxf(mx, v[u]);
    }
#pragma unroll
    for (int o = 16; o; o >>= 1) mx = fmaxf(mx, __shfl_xor_sync(0xffffffffu, mx, o));
    if ((t & 31) == 0) sred[t >> 5] = mx;
    __syncthreads();
    if (t < 8) {
        float m2 = sred[t];
#pragma unroll
        for (int o = 4; o; o >>= 1) m2 = fmaxf(m2, __shfl_xor_sync(0xffu, m2, o));
        if (t == 0) sred[0] = m2;
    }
    __syncthreads();
    mx = sred[0];

    float sum = 0.f;
#pragma unroll
    for (int u = 0; u < 8; u++) {
        int j = t + u * 256;
        if (j < valid) { v[u] = expf(v[u] - mx); sum += v[u]; }
    }
#pragma unroll
    for (int o = 16; o; o >>= 1) sum += __shfl_xor_sync(0xffffffffu, sum, o);
    __syncthreads();   // sred reuse
    if ((t & 31) == 0) sred[t >> 5] = sum;
    __syncthreads();
    if (t < 8) {
        float s2 = sred[t];
#pragma unroll
        for (int o = 4; o; o >>= 1) s2 += __shfl_xor_sync(0xffu, s2, o);
        if (t == 0) sred[0] = s2;
    }
    __syncthreads();
    float inv = 1.0f / sred[0];

#pragma unroll
    for (int u = 0; u < 8; u++) {
        int j = t + u * 256;
        p[j] = (j < valid) ? v[u] * inv : 0.f;
    }
}

// ---------------------------------------------------------------------------
// Launch. Input order: x, q_w, q_b, k_w, k_b, ln_w, ln_b, embed_positions,
// position_ids. Output: q (B,H,S,D) | k (B,H,S,D) | attn (B,H,S,S), fp32.
// ---------------------------------------------------------------------------
extern "C" void kernel_launch(void* const* d_in, const int* in_sizes, int n_in,
                              void* d_out, int out_size) {
    const float* x   = (const float*)d_in[0];
    const float* qw  = (const float*)d_in[1];
    const float* qb  = (const float*)d_in[2];
    const float* kw  = (const float*)d_in[3];
    const float* kb  = (const float*)d_in[4];
    const float* lnw = (const float*)d_in[5];
    const float* lnb = (const float*)d_in[6];
    const float* ep  = (const float*)d_in[7];
    const int*   pid = (const int*)d_in[8];

    float* oq = (float*)d_out;
    float* ok = oq + (size_t)BB * HH * SS * DD;
    float* oa = ok + (size_t)BB * HH * SS * DD;

    ln_kernel<<<NTOK, 256>>>(x, lnw, lnb);

    dim3 gproj(EE / 128, NTOK / 128);
    proj_kernel<<<gproj, 256>>>(qw, qb, ep, pid, oq);
    proj_kernel<<<gproj, 256>>>(kw, kb, ep, pid, ok);

    dim3 gsc(SS / 128, SS / 128, BB * HH);
    scores_kernel<<<gsc, 256>>>(oq, ok, oa);

    softmax_kernel<<<BB * HH * SS, 256>>>(oa);
}

// round 7
// speedup vs baseline: 1.4259x; 1.4259x over previous
#include <cuda_runtime.h>
#include <cuda_bf16.h>
#include <stdint.h>

// Problem constants
#define BB   2
#define SS   2048
#define EE   4096
#define HH   16
#define DD   256
#define RR   64
#define NTOK (BB * SS)
#define NEG_INF (-3.402823466e38f)

// ---------------------------------------------------------------------------
// Static device scratch (no allocation allowed)
// ---------------------------------------------------------------------------
__device__ __nv_bfloat16 g_xh[(size_t)NTOK * EE];   // xnorm hi
__device__ __nv_bfloat16 g_xl[(size_t)NTOK * EE];   // xnorm lo
__device__ __nv_bfloat16 g_wh[(size_t)EE * EE];     // current weight hi
__device__ __nv_bfloat16 g_wl[(size_t)EE * EE];     // current weight lo
__device__ __nv_bfloat16 g_qh[(size_t)BB * HH * SS * DD];
__device__ __nv_bfloat16 g_ql[(size_t)BB * HH * SS * DD];
__device__ __nv_bfloat16 g_kh[(size_t)BB * HH * SS * DD];
__device__ __nv_bfloat16 g_kl[(size_t)BB * HH * SS * DD];

// ---------------------------------------------------------------------------
// PTX helpers (all sm_80-baseline instructions — no 'a'-gated features)
// ---------------------------------------------------------------------------
__device__ __forceinline__ uint32_t smem_u32(const void* p) {
    uint32_t a;
    asm("{ .reg .u64 t; cvta.to.shared.u64 t, %1; cvt.u32.u64 %0, t; }"
        : "=r"(a) : "l"(p));
    return a;
}
__device__ __forceinline__ void ldsm4(uint32_t* r, uint32_t addr) {
    asm volatile("ldmatrix.sync.aligned.m8n8.x4.shared.b16 {%0,%1,%2,%3}, [%4];"
                 : "=r"(r[0]), "=r"(r[1]), "=r"(r[2]), "=r"(r[3]) : "r"(addr));
}
__device__ __forceinline__ void mma16816(float* c, const uint32_t* a,
                                         uint32_t b0, uint32_t b1) {
    asm volatile("mma.sync.aligned.m16n8k16.row.col.f32.bf16.bf16.f32 "
                 "{%0,%1,%2,%3}, {%4,%5,%6,%7}, {%8,%9}, {%0,%1,%2,%3};"
                 : "+f"(c[0]), "+f"(c[1]), "+f"(c[2]), "+f"(c[3])
                 : "r"(a[0]), "r"(a[1]), "r"(a[2]), "r"(a[3]), "r"(b0), "r"(b1));
}
__device__ __forceinline__ void cp16(uint32_t s, const void* g) {
    asm volatile("cp.async.cg.shared.global [%0], [%1], 16;"
                 :: "r"(s), "l"(__cvta_generic_to_global(g)));
}
#define CP_COMMIT() asm volatile("cp.async.commit_group;")
#define CP_WAIT(N)  asm volatile("cp.async.wait_group %0;" :: "n"(N))

// Split two fp32 into packed bf16 hi and lo pairs.
__device__ __forceinline__ uint32_t pack_hilo(float a, float b, uint32_t& lo) {
    __nv_bfloat16 ha = __float2bfloat16_rn(a), hb = __float2bfloat16_rn(b);
    __nv_bfloat16 la = __float2bfloat16_rn(a - __bfloat162float(ha));
    __nv_bfloat16 lb = __float2bfloat16_rn(b - __bfloat162float(hb));
    lo = (uint32_t)__bfloat16_as_ushort(la) | ((uint32_t)__bfloat16_as_ushort(lb) << 16);
    return (uint32_t)__bfloat16_as_ushort(ha) | ((uint32_t)__bfloat16_as_ushort(hb) << 16);
}

// ---------------------------------------------------------------------------
// Shared GEMM machinery: 128x128 tile, BK=32, 8 warps (warp tile 64x32),
// bf16x3 split, double-buffered cp.async.
// Smem: per stage 4 tiles (Ahi,Alo,Bhi,Blo) of 128 rows x 40 bf16 (80B rows).
// ---------------------------------------------------------------------------
#define KPAD    40
#define TILE_B  (128 * KPAD * 2)     // 10240 bytes per tile
#define STAGE_B (4 * TILE_B)         // 40960
#define GSMEM   (2 * STAGE_B)        // 81920

__device__ __forceinline__ void load_stage(
    uint32_t sbase, int buf,
    const __nv_bfloat16* Ah, const __nv_bfloat16* Al,
    const __nv_bfloat16* Bh, const __nv_bfloat16* Bl,
    int lda, int kt, int lrow, int lch)
{
    uint32_t st = sbase + buf * STAGE_B + lrow * 80 + lch * 16;
    size_t go = (size_t)lrow * lda + kt * 32 + lch * 8;
    cp16(st,                  Ah + go);
    cp16(st + 16,             Ah + go + 8);
    cp16(st + TILE_B,         Al + go);
    cp16(st + TILE_B + 16,    Al + go + 8);
    cp16(st + 2 * TILE_B,     Bh + go);
    cp16(st + 2 * TILE_B + 16,Bh + go + 8);
    cp16(st + 3 * TILE_B,     Bl + go);
    cp16(st + 3 * TILE_B + 16,Bl + go + 8);
}

__device__ __forceinline__ void compute_stage(uint32_t sbase, int buf,
                                              int wm, int wn, int lane,
                                              float acc[4][4][4])
{
    uint32_t base = sbase + buf * STAGE_B;
    uint32_t rowoff = (lane & 15) * 80 + (lane >> 4) * 16;
#pragma unroll
    for (int kk = 0; kk < 2; kk++) {
        uint32_t bh[2][4], bl[2][4];
#pragma unroll
        for (int nt2 = 0; nt2 < 2; nt2++) {
            uint32_t ba = base + 2 * TILE_B + (wn * 32 + nt2 * 16) * 80 + kk * 32 + rowoff;
            ldsm4(bh[nt2], ba);
            ldsm4(bl[nt2], ba + TILE_B);
        }
#pragma unroll
        for (int mt = 0; mt < 4; mt++) {
            uint32_t ah[4], al[4];
            uint32_t aa = base + (wm * 64 + mt * 16) * 80 + kk * 32 + rowoff;
            ldsm4(ah, aa);
            ldsm4(al, aa + TILE_B);
#pragma unroll
            for (int nt = 0; nt < 4; nt++) {
                uint32_t b0h = bh[nt >> 1][nt & 1], b1h = bh[nt >> 1][(nt & 1) + 2];
                uint32_t b0l = bl[nt >> 1][nt & 1], b1l = bl[nt >> 1][(nt & 1) + 2];
                mma16816(acc[mt][nt], ah, b0h, b1h);   // hi*hi
                mma16816(acc[mt][nt], ah, b0l, b1l);   // hi*lo
                mma16816(acc[mt][nt], al, b0h, b1h);   // lo*hi
            }
        }
    }
}

__device__ __forceinline__ void gemm_mainloop(
    uint32_t sbase,
    const __nv_bfloat16* Ah, const __nv_bfloat16* Al,
    const __nv_bfloat16* Bh, const __nv_bfloat16* Bl,
    int lda, int nk, float acc[4][4][4])
{
    int tid = threadIdx.x, lane = tid & 31, wid = tid >> 5;
    int wm = wid & 1, wn = wid >> 1;
    int lrow = tid >> 1, lch = (tid & 1) * 2;

    load_stage(sbase, 0, Ah, Al, Bh, Bl, lda, 0, lrow, lch);
    CP_COMMIT();
    for (int kt = 0; kt < nk; kt++) {
        if (kt + 1 < nk) {
            load_stage(sbase, (kt + 1) & 1, Ah, Al, Bh, Bl, lda, kt + 1, lrow, lch);
            CP_COMMIT();
            CP_WAIT(1);
        } else {
            CP_WAIT(0);
        }
        __syncthreads();
        compute_stage(sbase, kt & 1, wm, wn, lane, acc);
        __syncthreads();
    }
}

// ---------------------------------------------------------------------------
// Kernel 1: LayerNorm -> bf16 hi/lo split output
// ---------------------------------------------------------------------------
__global__ void __launch_bounds__(256) ln_kernel(const float* __restrict__ x,
                                                 const float* __restrict__ lnw,
                                                 const float* __restrict__ lnb) {
    __shared__ float sred[16];
    int row = blockIdx.x;
    const float* xr = x + (size_t)row * EE;
    int t = threadIdx.x;

    float4 vv[4];
    float s = 0.f, ss = 0.f;
#pragma unroll
    for (int u = 0; u < 4; u++) {
        vv[u] = *(const float4*)(xr + u * 1024 + t * 4);
        s  += vv[u].x + vv[u].y + vv[u].z + vv[u].w;
        ss += vv[u].x * vv[u].x + vv[u].y * vv[u].y
            + vv[u].z * vv[u].z + vv[u].w * vv[u].w;
    }
#pragma unroll
    for (int o = 16; o; o >>= 1) {
        s  += __shfl_xor_sync(0xffffffffu, s, o);
        ss += __shfl_xor_sync(0xffffffffu, ss, o);
    }
    if ((t & 31) == 0) { sred[t >> 5] = s; sred[8 + (t >> 5)] = ss; }
    __syncthreads();
    if (t < 8) {
        float a = sred[t], b = sred[8 + t];
#pragma unroll
        for (int o = 4; o; o >>= 1) {
            a += __shfl_xor_sync(0xffu, a, o);
            b += __shfl_xor_sync(0xffu, b, o);
        }
        if (t == 0) { sred[0] = a; sred[8] = b; }
    }
    __syncthreads();
    float mean = sred[0] * (1.0f / EE);
    float var  = sred[8] * (1.0f / EE) - mean * mean;
    float inv  = rsqrtf(var + 1e-5f);

#pragma unroll
    for (int u = 0; u < 4; u++) {
        float4 w = *(const float4*)(lnw + u * 1024 + t * 4);
        float4 b = *(const float4*)(lnb + u * 1024 + t * 4);
        float o0 = (vv[u].x - mean) * inv * w.x + b.x;
        float o1 = (vv[u].y - mean) * inv * w.y + b.y;
        float o2 = (vv[u].z - mean) * inv * w.z + b.z;
        float o3 = (vv[u].w - mean) * inv * w.w + b.w;
        uint32_t l0, l1;
        uint32_t h0 = pack_hilo(o0, o1, l0);
        uint32_t h1 = pack_hilo(o2, o3, l1);
        size_t idx = (size_t)row * EE + u * 1024 + t * 4;
        *(uint2*)(g_xh + idx) = make_uint2(h0, h1);
        *(uint2*)(g_xl + idx) = make_uint2(l0, l1);
    }
}

// ---------------------------------------------------------------------------
// Kernel 1b: fp32 -> bf16 hi/lo weight conversion
// ---------------------------------------------------------------------------
__global__ void __launch_bounds__(256) cvt_kernel(const float* __restrict__ in) {
    size_t i = ((size_t)blockIdx.x * 256 + threadIdx.x) * 4;
    float4 v = *(const float4*)(in + i);
    uint32_t l0, l1;
    uint32_t h0 = pack_hilo(v.x, v.y, l0);
    uint32_t h1 = pack_hilo(v.z, v.w, l1);
    *(uint2*)(g_wh + i) = make_uint2(h0, h1);
    *(uint2*)(g_wl + i) = make_uint2(l0, l1);
}

// ---------------------------------------------------------------------------
// Kernel 2: projection GEMM (mma.sync bf16x3) + bias + RoPE + transpose.
// Also emits bf16 hi/lo copies of the output for the scores GEMM.
// sel: 0 -> write g_qh/g_ql, 1 -> g_kh/g_kl.
// ---------------------------------------------------------------------------
__global__ void __launch_bounds__(256) proj_mma(const float* __restrict__ bias,
                                                const float* __restrict__ ep,
                                                const int* __restrict__ pid,
                                                float* __restrict__ out, int sel) {
    extern __shared__ char smem[];
    uint32_t sbase = smem_u32(smem);
    int bm = blockIdx.y * 128, bn = blockIdx.x * 128;

    float acc[4][4][4];
#pragma unroll
    for (int i = 0; i < 4; i++)
#pragma unroll
        for (int j = 0; j < 4; j++)
#pragma unroll
            for (int k = 0; k < 4; k++) acc[i][j][k] = 0.f;

    gemm_mainloop(sbase,
                  g_xh + (size_t)bm * EE, g_xl + (size_t)bm * EE,
                  g_wh + (size_t)bn * EE, g_wl + (size_t)bn * EE,
                  EE, EE / 32, acc);

    __nv_bfloat16* ohh = sel ? g_kh : g_qh;
    __nv_bfloat16* oll = sel ? g_kl : g_ql;

    int tid = threadIdx.x, lane = tid & 31, wid = tid >> 5;
    int wm = wid & 1, wn = wid >> 1;

#pragma unroll
    for (int mt = 0; mt < 4; mt++)
#pragma unroll
        for (int half = 0; half < 2; half++) {
            int row = bm + wm * 64 + mt * 16 + (lane >> 2) + half * 8;
            int bb = row >> 11, s = row & (SS - 1);
            int pos = pid[row];
            const float* epp = ep + (size_t)pos * RR;
#pragma unroll
            for (int nt = 0; nt < 4; nt++) {
                int c = bn + wn * 32 + nt * 8 + (lane & 3) * 2;
                float2 bv = *(const float2*)(bias + c);
                float v0 = acc[mt][nt][half * 2 + 0] + bv.x;
                float v1 = acc[mt][nt][half * 2 + 1] + bv.y;
                int h = c >> 8, d = c & 255;
                if (d < RR) {
                    int j = d >> 1;
                    float sv = epp[j], cv = epp[32 + j];
                    float t0 = v0, t1 = v1;
                    v0 = t0 * cv - t1 * sv;
                    v1 = t1 * cv + t0 * sv;
                }
                size_t o = (((size_t)(bb * HH + h)) * SS + s) * DD + d;
                *(float2*)(out + o) = make_float2(v0, v1);
                uint32_t lo, hi = pack_hilo(v0, v1, lo);
                *(uint32_t*)(ohh + o) = hi;
                *(uint32_t*)(oll + o) = lo;
            }
        }
}

// ---------------------------------------------------------------------------
// Kernel 3: causal scores GEMM (mma.sync bf16x3), K=256.
// ---------------------------------------------------------------------------
__global__ void __launch_bounds__(256) scores_mma(float* __restrict__ attn) {
    if (blockIdx.x > blockIdx.y) return;   // fully masked tile
    extern __shared__ char smem[];
    uint32_t sbase = smem_u32(smem);
    int bh = blockIdx.z;
    int bm = blockIdx.y * 128, bn = blockIdx.x * 128;

    float acc[4][4][4];
#pragma unroll
    for (int i = 0; i < 4; i++)
#pragma unroll
        for (int j = 0; j < 4; j++)
#pragma unroll
            for (int k = 0; k < 4; k++) acc[i][j][k] = 0.f;

    size_t qb = (size_t)bh * SS * DD + (size_t)bm * DD;
    size_t kb = (size_t)bh * SS * DD + (size_t)bn * DD;
    gemm_mainloop(sbase, g_qh + qb, g_ql + qb, g_kh + kb, g_kl + kb,
                  DD, DD / 32, acc);

    int tid = threadIdx.x, lane = tid & 31, wid = tid >> 5;
    int wm = wid & 1, wn = wid >> 1;
    float* C = attn + (size_t)bh * SS * SS;

#pragma unroll
    for (int mt = 0; mt < 4; mt++)
#pragma unroll
        for (int half = 0; half < 2; half++) {
            int row = bm + wm * 64 + mt * 16 + (lane >> 2) + half * 8;
#pragma unroll
            for (int nt = 0; nt < 4; nt++) {
                int c = bn + wn * 32 + nt * 8 + (lane & 3) * 2;
                *(float2*)(C + (size_t)row * SS + c) = make_float2(
                    acc[mt][nt][half * 2 + 0] * 0.0625f,
                    acc[mt][nt][half * 2 + 1] * 0.0625f);
            }
        }
}

// ---------------------------------------------------------------------------
// Kernel 4: in-place causal softmax
// ---------------------------------------------------------------------------
__global__ void __launch_bounds__(256) softmax_kernel(float* __restrict__ attn) {
    __shared__ float sred[8];
    int r = blockIdx.x;
    int i = r & (SS - 1);
    float* p = attn + (size_t)r * SS;
    int valid = i + 1;
    int t = threadIdx.x;

    float v[8];
    float mx = NEG_INF;
#pragma unroll
    for (int u = 0; u < 8; u++) {
        int j = t + u * 256;
        v[u] = (j < valid) ? p[j] : NEG_INF;
        mx = fmaxf(mx, v[u]);
    }
#pragma unroll
    for (int o = 16; o; o >>= 1) mx = fmaxf(mx, __shfl_xor_sync(0xffffffffu, mx, o));
    if ((t & 31) == 0) sred[t >> 5] = mx;
    __syncthreads();
    if (t < 8) {
        float m2 = sred[t];
#pragma unroll
        for (int o = 4; o; o >>= 1) m2 = fmaxf(m2, __shfl_xor_sync(0xffu, m2, o));
        if (t == 0) sred[0] = m2;
    }
    __syncthreads();
    mx = sred[0];

    float sum = 0.f;
#pragma unroll
    for (int u = 0; u < 8; u++) {
        int j = t + u * 256;
        if (j < valid) { v[u] = expf(v[u] - mx); sum += v[u]; }
    }
#pragma unroll
    for (int o = 16; o; o >>= 1) sum += __shfl_xor_sync(0xffffffffu, sum, o);
    __syncthreads();
    if ((t & 31) == 0) sred[t >> 5] = sum;
    __syncthreads();
    if (t < 8) {
        float s2 = sred[t];
#pragma unroll
        for (int o = 4; o; o >>= 1) s2 += __shfl_xor_sync(0xffu, s2, o);
        if (t == 0) sred[0] = s2;
    }
    __syncthreads();
    float inv = 1.0f / sred[0];

#pragma unroll
    for (int u = 0; u < 8; u++) {
        int j = t + u * 256;
        p[j] = (j < valid) ? v[u] * inv : 0.f;
    }
}

// ---------------------------------------------------------------------------
// Launch
// ---------------------------------------------------------------------------
extern "C" void kernel_launch(void* const* d_in, const int* in_sizes, int n_in,
                              void* d_out, int out_size) {
    const float* x   = (const float*)d_in[0];
    const float* qw  = (const float*)d_in[1];
    const float* qb  = (const float*)d_in[2];
    const float* kw  = (const float*)d_in[3];
    const float* kb  = (const float*)d_in[4];
    const float* lnw = (const float*)d_in[5];
    const float* lnb = (const float*)d_in[6];
    const float* ep  = (const float*)d_in[7];
    const int*   pid = (const int*)d_in[8];

    float* oq = (float*)d_out;
    float* ok = oq + (size_t)BB * HH * SS * DD;
    float* oa = ok + (size_t)BB * HH * SS * DD;

    cudaFuncSetAttribute(proj_mma,   cudaFuncAttributeMaxDynamicSharedMemorySize, GSMEM);
    cudaFuncSetAttribute(scores_mma, cudaFuncAttributeMaxDynamicSharedMemorySize, GSMEM);

    ln_kernel<<<NTOK, 256>>>(x, lnw, lnb);

    dim3 gproj(EE / 128, NTOK / 128);
    cvt_kernel<<<(int)((size_t)EE * EE / 1024), 256>>>(qw);
    proj_mma<<<gproj, 256, GSMEM>>>(qb, ep, pid, oq, 0);
    cvt_kernel<<<(int)((size_t)EE * EE / 1024), 256>>>(kw);
    proj_mma<<<gproj, 256, GSMEM>>>(kb, ep, pid, ok, 1);

    dim3 gsc(SS / 128, SS / 128, BB * HH);
    scores_mma<<<gsc, 256, GSMEM>>>(oa);

    softmax_kernel<<<BB * HH * SS, 256>>>(oa);
}

// round 9
// speedup vs baseline: 1.9569x; 1.3724x over previous
#include <cuda_runtime.h>
#include <cuda_bf16.h>
#include <stdint.h>

// Problem constants
#define BB   2
#define SS   2048
#define EE   4096
#define HH   16
#define DD   256
#define RR   64
#define NTOK (BB * SS)
#define NEG_INF (-3.402823466e38f)

// ---------------------------------------------------------------------------
// Static device scratch (no allocation allowed)
// ---------------------------------------------------------------------------
__device__ __nv_bfloat16 g_xh[(size_t)NTOK * EE];   // xnorm hi
__device__ __nv_bfloat16 g_xl[(size_t)NTOK * EE];   // xnorm lo
__device__ __nv_bfloat16 g_wh[(size_t)EE * EE];     // current weight hi
__device__ __nv_bfloat16 g_wl[(size_t)EE * EE];     // current weight lo
__device__ __nv_bfloat16 g_qh[(size_t)BB * HH * SS * DD];
__device__ __nv_bfloat16 g_ql[(size_t)BB * HH * SS * DD];
__device__ __nv_bfloat16 g_kh[(size_t)BB * HH * SS * DD];
__device__ __nv_bfloat16 g_kl[(size_t)BB * HH * SS * DD];

// ---------------------------------------------------------------------------
// PTX helpers (all sm_80-baseline instructions — no 'a'-gated features)
// ---------------------------------------------------------------------------
__device__ __forceinline__ uint32_t smem_u32(const void* p) {
    uint32_t a;
    asm("{ .reg .u64 t; cvta.to.shared.u64 t, %1; cvt.u32.u64 %0, t; }"
        : "=r"(a) : "l"(p));
    return a;
}
__device__ __forceinline__ void ldsm4(uint32_t* r, uint32_t addr) {
    asm volatile("ldmatrix.sync.aligned.m8n8.x4.shared.b16 {%0,%1,%2,%3}, [%4];"
                 : "=r"(r[0]), "=r"(r[1]), "=r"(r[2]), "=r"(r[3]) : "r"(addr));
}
__device__ __forceinline__ void mma16816(float* c, const uint32_t* a,
                                         uint32_t b0, uint32_t b1) {
    asm volatile("mma.sync.aligned.m16n8k16.row.col.f32.bf16.bf16.f32 "
                 "{%0,%1,%2,%3}, {%4,%5,%6,%7}, {%8,%9}, {%0,%1,%2,%3};"
                 : "+f"(c[0]), "+f"(c[1]), "+f"(c[2]), "+f"(c[3])
                 : "r"(a[0]), "r"(a[1]), "r"(a[2]), "r"(a[3]), "r"(b0), "r"(b1));
}
__device__ __forceinline__ void cp16(uint32_t s, const void* g) {
    asm volatile("cp.async.cg.shared.global [%0], [%1], 16;"
                 :: "r"(s), "l"(__cvta_generic_to_global(g)));
}
#define CP_COMMIT() asm volatile("cp.async.commit_group;")
#define CP_WAIT(N)  asm volatile("cp.async.wait_group %0;" :: "n"(N))

// Split two fp32 into packed bf16 hi and lo pairs.
__device__ __forceinline__ uint32_t pack_hilo(float a, float b, uint32_t& lo) {
    __nv_bfloat16 ha = __float2bfloat16_rn(a), hb = __float2bfloat16_rn(b);
    __nv_bfloat16 la = __float2bfloat16_rn(a - __bfloat162float(ha));
    __nv_bfloat16 lb = __float2bfloat16_rn(b - __bfloat162float(hb));
    lo = (uint32_t)__bfloat16_as_ushort(la) | ((uint32_t)__bfloat16_as_ushort(lb) << 16);
    return (uint32_t)__bfloat16_as_ushort(ha) | ((uint32_t)__bfloat16_as_ushort(hb) << 16);
}

// ---------------------------------------------------------------------------
// Shared GEMM machinery: 128x128 tile, BK=32, 8 warps (warp tile 64x32),
// bf16x3 split, 3-stage cp.async pipeline, ONE __syncthreads per stage.
// Smem: per stage 4 tiles (Ahi,Alo,Bhi,Blo) of 128 rows x 40 bf16 (80B rows).
// ---------------------------------------------------------------------------
#define KPAD    40
#define TILE_B  (128 * KPAD * 2)     // 10240 bytes per tile
#define STAGE_B (4 * TILE_B)         // 40960
#define NSTAGE  3
#define GSMEM   (NSTAGE * STAGE_B)   // 122880

__device__ __forceinline__ void load_stage(
    uint32_t sbase, int buf,
    const __nv_bfloat16* Ah, const __nv_bfloat16* Al,
    const __nv_bfloat16* Bh, const __nv_bfloat16* Bl,
    int lda, int kt, int lrow, int lch)
{
    uint32_t st = sbase + buf * STAGE_B + lrow * 80 + lch * 16;
    size_t go = (size_t)lrow * lda + kt * 32 + lch * 8;
    cp16(st,                  Ah + go);
    cp16(st + 16,             Ah + go + 8);
    cp16(st + TILE_B,         Al + go);
    cp16(st + TILE_B + 16,    Al + go + 8);
    cp16(st + 2 * TILE_B,     Bh + go);
    cp16(st + 2 * TILE_B + 16,Bh + go + 8);
    cp16(st + 3 * TILE_B,     Bl + go);
    cp16(st + 3 * TILE_B + 16,Bl + go + 8);
}

__device__ __forceinline__ void compute_stage(uint32_t sbase, int buf,
                                              int wm, int wn, int lane,
                                              float acc[4][4][4])
{
    uint32_t base = sbase + buf * STAGE_B;
    uint32_t rowoff = (lane & 15) * 80 + (lane >> 4) * 16;
#pragma unroll
    for (int kk = 0; kk < 2; kk++) {
        uint32_t bh[2][4], bl[2][4];
#pragma unroll
        for (int nt2 = 0; nt2 < 2; nt2++) {
            uint32_t ba = base + 2 * TILE_B + (wn * 32 + nt2 * 16) * 80 + kk * 32 + rowoff;
            ldsm4(bh[nt2], ba);
            ldsm4(bl[nt2], ba + TILE_B);
        }
#pragma unroll
        for (int mt = 0; mt < 4; mt++) {
            uint32_t ah[4], al[4];
            uint32_t aa = base + (wm * 64 + mt * 16) * 80 + kk * 32 + rowoff;
            ldsm4(ah, aa);
            ldsm4(al, aa + TILE_B);
#pragma unroll
            for (int nt = 0; nt < 4; nt++) {
                uint32_t b0h = bh[nt >> 1][nt & 1], b1h = bh[nt >> 1][(nt & 1) + 2];
                uint32_t b0l = bl[nt >> 1][nt & 1], b1l = bl[nt >> 1][(nt & 1) + 2];
                mma16816(acc[mt][nt], ah, b0h, b1h);   // hi*hi
                mma16816(acc[mt][nt], ah, b0l, b1l);   // hi*lo
                mma16816(acc[mt][nt], al, b0h, b1h);   // lo*hi
            }
        }
    }
}

// 3-stage pipeline, one __syncthreads per iteration. An (possibly empty)
// commit_group is issued every iteration so wait_group<1> at iteration kt
// always means "stage kt's loads have landed".
__device__ __forceinline__ void gemm_mainloop(
    uint32_t sbase,
    const __nv_bfloat16* Ah, const __nv_bfloat16* Al,
    const __nv_bfloat16* Bh, const __nv_bfloat16* Bl,
    int lda, int nk, float acc[4][4][4])
{
    int tid = threadIdx.x, lane = tid & 31, wid = tid >> 5;
    int wm = wid & 1, wn = wid >> 1;
    int lrow = tid >> 1, lch = (tid & 1) * 2;

    load_stage(sbase, 0, Ah, Al, Bh, Bl, lda, 0, lrow, lch);
    CP_COMMIT();
    if (nk > 1) load_stage(sbase, 1, Ah, Al, Bh, Bl, lda, 1, lrow, lch);
    CP_COMMIT();

    int buf = 0, nbuf = 2;
#pragma unroll 1
    for (int kt = 0; kt < nk; kt++) {
        CP_WAIT(1);                 // stage kt resident (group kt retired)
        __syncthreads();            // all warps done with buffer `nbuf` too
        if (kt + 2 < nk)
            load_stage(sbase, nbuf, Ah, Al, Bh, Bl, lda, kt + 2, lrow, lch);
        CP_COMMIT();                // empty near the tail — keeps counts exact
        compute_stage(sbase, buf, wm, wn, lane, acc);
        buf = (buf == NSTAGE - 1) ? 0 : buf + 1;
        nbuf = (nbuf == NSTAGE - 1) ? 0 : nbuf + 1;
    }
}

// ---------------------------------------------------------------------------
// Kernel 1: LayerNorm -> bf16 hi/lo split output
// ---------------------------------------------------------------------------
__global__ void __launch_bounds__(256) ln_kernel(const float* __restrict__ x,
                                                 const float* __restrict__ lnw,
                                                 const float* __restrict__ lnb) {
    __shared__ float sred[16];
    int row = blockIdx.x;
    const float* xr = x + (size_t)row * EE;
    int t = threadIdx.x;

    float4 vv[4];
    float s = 0.f, ss = 0.f;
#pragma unroll
    for (int u = 0; u < 4; u++) {
        vv[u] = *(const float4*)(xr + u * 1024 + t * 4);
        s  += vv[u].x + vv[u].y + vv[u].z + vv[u].w;
        ss += vv[u].x * vv[u].x + vv[u].y * vv[u].y
            + vv[u].z * vv[u].z + vv[u].w * vv[u].w;
    }
#pragma unroll
    for (int o = 16; o; o >>= 1) {
        s  += __shfl_xor_sync(0xffffffffu, s, o);
        ss += __shfl_xor_sync(0xffffffffu, ss, o);
    }
    if ((t & 31) == 0) { sred[t >> 5] = s; sred[8 + (t >> 5)] = ss; }
    __syncthreads();
    if (t < 8) {
        float a = sred[t], b = sred[8 + t];
#pragma unroll
        for (int o = 4; o; o >>= 1) {
            a += __shfl_xor_sync(0xffu, a, o);
            b += __shfl_xor_sync(0xffu, b, o);
        }
        if (t == 0) { sred[0] = a; sred[8] = b; }
    }
    __syncthreads();
    float mean = sred[0] * (1.0f / EE);
    float var  = sred[8] * (1.0f / EE) - mean * mean;
    float inv  = rsqrtf(var + 1e-5f);

#pragma unroll
    for (int u = 0; u < 4; u++) {
        float4 w = *(const float4*)(lnw + u * 1024 + t * 4);
        float4 b = *(const float4*)(lnb + u * 1024 + t * 4);
        float o0 = (vv[u].x - mean) * inv * w.x + b.x;
        float o1 = (vv[u].y - mean) * inv * w.y + b.y;
        float o2 = (vv[u].z - mean) * inv * w.z + b.z;
        float o3 = (vv[u].w - mean) * inv * w.w + b.w;
        uint32_t l0, l1;
        uint32_t h0 = pack_hilo(o0, o1, l0);
        uint32_t h1 = pack_hilo(o2, o3, l1);
        size_t idx = (size_t)row * EE + u * 1024 + t * 4;
        *(uint2*)(g_xh + idx) = make_uint2(h0, h1);
        *(uint2*)(g_xl + idx) = make_uint2(l0, l1);
    }
}

// ---------------------------------------------------------------------------
// Kernel 1b: fp32 -> bf16 hi/lo weight conversion
// ---------------------------------------------------------------------------
__global__ void __launch_bounds__(256) cvt_kernel(const float* __restrict__ in) {
    size_t i = ((size_t)blockIdx.x * 256 + threadIdx.x) * 4;
    float4 v = *(const float4*)(in + i);
    uint32_t l0, l1;
    uint32_t h0 = pack_hilo(v.x, v.y, l0);
    uint32_t h1 = pack_hilo(v.z, v.w, l1);
    *(uint2*)(g_wh + i) = make_uint2(h0, h1);
    *(uint2*)(g_wl + i) = make_uint2(l0, l1);
}

// ---------------------------------------------------------------------------
// Kernel 2: projection GEMM (mma.sync bf16x3) + bias + RoPE + transpose.
// Also emits bf16 hi/lo copies of the output for the scores GEMM.
// sel: 0 -> write g_qh/g_ql, 1 -> g_kh/g_kl.
// ---------------------------------------------------------------------------
__global__ void __launch_bounds__(256) proj_mma(const float* __restrict__ bias,
                                                const float* __restrict__ ep,
                                                const int* __restrict__ pid,
                                                float* __restrict__ out, int sel) {
    extern __shared__ char smem[];
    uint32_t sbase = smem_u32(smem);
    int bm = blockIdx.y * 128, bn = blockIdx.x * 128;

    float acc[4][4][4];
#pragma unroll
    for (int i = 0; i < 4; i++)
#pragma unroll
        for (int j = 0; j < 4; j++)
#pragma unroll
            for (int k = 0; k < 4; k++) acc[i][j][k] = 0.f;

    gemm_mainloop(sbase,
                  g_xh + (size_t)bm * EE, g_xl + (size_t)bm * EE,
                  g_wh + (size_t)bn * EE, g_wl + (size_t)bn * EE,
                  EE, EE / 32, acc);

    __nv_bfloat16* ohh = sel ? g_kh : g_qh;
    __nv_bfloat16* oll = sel ? g_kl : g_ql;

    int tid = threadIdx.x, lane = tid & 31, wid = tid >> 5;
    int wm = wid & 1, wn = wid >> 1;

#pragma unroll
    for (int mt = 0; mt < 4; mt++)
#pragma unroll
        for (int half = 0; half < 2; half++) {
            int row = bm + wm * 64 + mt * 16 + (lane >> 2) + half * 8;
            int bb = row >> 11, s = row & (SS - 1);
            int pos = pid[row];
            const float* epp = ep + (size_t)pos * RR;
#pragma unroll
            for (int nt = 0; nt < 4; nt++) {
                int c = bn + wn * 32 + nt * 8 + (lane & 3) * 2;
                float2 bv = *(const float2*)(bias + c);
                float v0 = acc[mt][nt][half * 2 + 0] + bv.x;
                float v1 = acc[mt][nt][half * 2 + 1] + bv.y;
                int h = c >> 8, d = c & 255;
                if (d < RR) {
                    int j = d >> 1;
                    float sv = epp[j], cv = epp[32 + j];
                    float t0 = v0, t1 = v1;
                    v0 = t0 * cv - t1 * sv;
                    v1 = t1 * cv + t0 * sv;
                }
                size_t o = (((size_t)(bb * HH + h)) * SS + s) * DD + d;
                *(float2*)(out + o) = make_float2(v0, v1);
                uint32_t lo, hi = pack_hilo(v0, v1, lo);
                *(uint32_t*)(ohh + o) = hi;
                *(uint32_t*)(oll + o) = lo;
            }
        }
}

// ---------------------------------------------------------------------------
// Kernel 3: causal scores GEMM (mma.sync bf16x3), K=256.
// ---------------------------------------------------------------------------
__global__ void __launch_bounds__(256) scores_mma(float* __restrict__ attn) {
    if (blockIdx.x > blockIdx.y) return;   // fully masked tile
    extern __shared__ char smem[];
    uint32_t sbase = smem_u32(smem);
    int bh = blockIdx.z;
    int bm = blockIdx.y * 128, bn = blockIdx.x * 128;

    float acc[4][4][4];
#pragma unroll
    for (int i = 0; i < 4; i++)
#pragma unroll
        for (int j = 0; j < 4; j++)
#pragma unroll
            for (int k = 0; k < 4; k++) acc[i][j][k] = 0.f;

    size_t qb = (size_t)bh * SS * DD + (size_t)bm * DD;
    size_t kb = (size_t)bh * SS * DD + (size_t)bn * DD;
    gemm_mainloop(sbase, g_qh + qb, g_ql + qb, g_kh + kb, g_kl + kb,
                  DD, DD / 32, acc);

    int tid = threadIdx.x, lane = tid & 31, wid = tid >> 5;
    int wm = wid & 1, wn = wid >> 1;
    float* C = attn + (size_t)bh * SS * SS;

#pragma unroll
    for (int mt = 0; mt < 4; mt++)
#pragma unroll
        for (int half = 0; half < 2; half++) {
            int row = bm + wm * 64 + mt * 16 + (lane >> 2) + half * 8;
#pragma unroll
            for (int nt = 0; nt < 4; nt++) {
                int c = bn + wn * 32 + nt * 8 + (lane & 3) * 2;
                *(float2*)(C + (size_t)row * SS + c) = make_float2(
                    acc[mt][nt][half * 2 + 0] * 0.0625f,
                    acc[mt][nt][half * 2 + 1] * 0.0625f);
            }
        }
}

// ---------------------------------------------------------------------------
// Kernel 4: in-place causal softmax
// ---------------------------------------------------------------------------
__global__ void __launch_bounds__(256) softmax_kernel(float* __restrict__ attn) {
    __shared__ float sred[8];
    int r = blockIdx.x;
    int i = r & (SS - 1);
    float* p = attn + (size_t)r * SS;
    int valid = i + 1;
    int t = threadIdx.x;

    float v[8];
    float mx = NEG_INF;
#pragma unroll
    for (int u = 0; u < 8; u++) {
        int j = t + u * 256;
        v[u] = (j < valid) ? p[j] : NEG_INF;
        mx = fmaxf(mx, v[u]);
    }
#pragma unroll
    for (int o = 16; o; o >>= 1) mx = fmaxf(mx, __shfl_xor_sync(0xffffffffu, mx, o));
    if ((t & 31) == 0) sred[t >> 5] = mx;
    __syncthreads();
    if (t < 8) {
        float m2 = sred[t];
#pragma unroll
        for (int o = 4; o; o >>= 1) m2 = fmaxf(m2, __shfl_xor_sync(0xffu, m2, o));
        if (t == 0) sred[0] = m2;
    }
    __syncthreads();
    mx = sred[0];

    float sum = 0.f;
#pragma unroll
    for (int u = 0; u < 8; u++) {
        int j = t + u * 256;
        if (j < valid) { v[u] = expf(v[u] - mx); sum += v[u]; }
    }
#pragma unroll
    for (int o = 16; o; o >>= 1) sum += __shfl_xor_sync(0xffffffffu, sum, o);
    __syncthreads();
    if ((t & 31) == 0) sred[t >> 5] = sum;
    __syncthreads();
    if (t < 8) {
        float s2 = sred[t];
#pragma unroll
        for (int o = 4; o; o >>= 1) s2 += __shfl_xor_sync(0xffu, s2, o);
        if (t == 0) sred[0] = s2;
    }
    __syncthreads();
    float inv = 1.0f / sred[0];

#pragma unroll
    for (int u = 0; u < 8; u++) {
        int j = t + u * 256;
        p[j] = (j < valid) ? v[u] * inv : 0.f;
    }
}

// ---------------------------------------------------------------------------
// Launch
// ---------------------------------------------------------------------------
extern "C" void kernel_launch(void* const* d_in, const int* in_sizes, int n_in,
                              void* d_out, int out_size) {
    const float* x   = (const float*)d_in[0];
    const float* qw  = (const float*)d_in[1];
    const float* qb  = (const float*)d_in[2];
    const float* kw  = (const float*)d_in[3];
    const float* kb  = (const float*)d_in[4];
    const float* lnw = (const float*)d_in[5];
    const float* lnb = (const float*)d_in[6];
    const float* ep  = (const float*)d_in[7];
    const int*   pid = (const int*)d_in[8];

    float* oq = (float*)d_out;
    float* ok = oq + (size_t)BB * HH * SS * DD;
    float* oa = ok + (size_t)BB * HH * SS * DD;

    cudaFuncSetAttribute(proj_mma,   cudaFuncAttributeMaxDynamicSharedMemorySize, GSMEM);
    cudaFuncSetAttribute(scores_mma, cudaFuncAttributeMaxDynamicSharedMemorySize, GSMEM);

    ln_kernel<<<NTOK, 256>>>(x, lnw, lnb);

    dim3 gproj(EE / 128, NTOK / 128);
    cvt_kernel<<<(int)((size_t)EE * EE / 1024), 256>>>(qw);
    proj_mma<<<gproj, 256, GSMEM>>>(qb, ep, pid, oq, 0);
    cvt_kernel<<<(int)((size_t)EE * EE / 1024), 256>>>(kw);
    proj_mma<<<gproj, 256, GSMEM>>>(kb, ep, pid, ok, 1);

    dim3 gsc(SS / 128, SS / 128, BB * HH);
    scores_mma<<<gsc, 256, GSMEM>>>(oa);

    softmax_kernel<<<BB * HH * SS, 256>>>(oa);
}

// round 10
// speedup vs baseline: 1.9935x; 1.0187x over previous
#include <cuda_runtime.h>
#include <cuda_bf16.h>
#include <stdint.h>

// Problem constants
#define BB   2
#define SS   2048
#define EE   4096
#define HH   16
#define DD   256
#define RR   64
#define NTOK (BB * SS)
#define NEG_INF (-3.402823466e38f)

// ---------------------------------------------------------------------------
// Static device scratch (no allocation allowed)
// ---------------------------------------------------------------------------
__device__ __nv_bfloat16 g_xh[(size_t)NTOK * EE];        // xnorm hi
__device__ __nv_bfloat16 g_xl[(size_t)NTOK * EE];        // xnorm lo
__device__ __nv_bfloat16 g_wh[2 * (size_t)EE * EE];      // q|k weight hi
__device__ __nv_bfloat16 g_wl[2 * (size_t)EE * EE];      // q|k weight lo
__device__ __nv_bfloat16 g_qh[(size_t)BB * HH * SS * DD];
__device__ __nv_bfloat16 g_ql[(size_t)BB * HH * SS * DD];
__device__ __nv_bfloat16 g_kh[(size_t)BB * HH * SS * DD];
__device__ __nv_bfloat16 g_kl[(size_t)BB * HH * SS * DD];

// ---------------------------------------------------------------------------
// PTX helpers (sm_80-baseline only)
// ---------------------------------------------------------------------------
__device__ __forceinline__ uint32_t smem_u32(const void* p) {
    uint32_t a;
    asm("{ .reg .u64 t; cvta.to.shared.u64 t, %1; cvt.u32.u64 %0, t; }"
        : "=r"(a) : "l"(p));
    return a;
}
__device__ __forceinline__ void ldsm4(uint32_t* r, uint32_t addr) {
    asm volatile("ldmatrix.sync.aligned.m8n8.x4.shared.b16 {%0,%1,%2,%3}, [%4];"
                 : "=r"(r[0]), "=r"(r[1]), "=r"(r[2]), "=r"(r[3]) : "r"(addr));
}
__device__ __forceinline__ void mma16816(float* c, const uint32_t* a,
                                         uint32_t b0, uint32_t b1) {
    asm volatile("mma.sync.aligned.m16n8k16.row.col.f32.bf16.bf16.f32 "
                 "{%0,%1,%2,%3}, {%4,%5,%6,%7}, {%8,%9}, {%0,%1,%2,%3};"
                 : "+f"(c[0]), "+f"(c[1]), "+f"(c[2]), "+f"(c[3])
                 : "r"(a[0]), "r"(a[1]), "r"(a[2]), "r"(a[3]), "r"(b0), "r"(b1));
}
__device__ __forceinline__ void cp16(uint32_t s, const void* g) {
    asm volatile("cp.async.cg.shared.global [%0], [%1], 16;"
                 :: "r"(s), "l"(__cvta_generic_to_global(g)));
}
#define CP_COMMIT() asm volatile("cp.async.commit_group;")
#define CP_WAIT(N)  asm volatile("cp.async.wait_group %0;" :: "n"(N))

__device__ __forceinline__ uint32_t pack_hilo(float a, float b, uint32_t& lo) {
    __nv_bfloat16 ha = __float2bfloat16_rn(a), hb = __float2bfloat16_rn(b);
    __nv_bfloat16 la = __float2bfloat16_rn(a - __bfloat162float(ha));
    __nv_bfloat16 lb = __float2bfloat16_rn(b - __bfloat162float(hb));
    lo = (uint32_t)__bfloat16_as_ushort(la) | ((uint32_t)__bfloat16_as_ushort(lb) << 16);
    return (uint32_t)__bfloat16_as_ushort(ha) | ((uint32_t)__bfloat16_as_ushort(hb) << 16);
}

// ---------------------------------------------------------------------------
// GEMM machinery: CTA tile 256x128, BK=32, 8 warps, warp tile 64x64,
// bf16x3 split, 3-stage cp.async pipeline, ONE __syncthreads per stage.
// Warp grid: wm = wid&3 (4 x 64 rows), wn = wid>>2 (2 x 64 cols).
// Smem stage: Ahi(20480) Alo(20480) Bhi(10240) Blo(10240) = 61440 B.
// ---------------------------------------------------------------------------
#define TM      256
#define TN      128
#define KPAD    40
#define ROWB    80                    // bytes per smem row (32 bf16 + pad)
#define OFF_AH  0
#define OFF_AL  (TM * ROWB)           // 20480
#define OFF_BH  (2 * TM * ROWB)      // 40960
#define OFF_BL  (2 * TM * ROWB + TN * ROWB)  // 51200
#define STAGE_B (2 * TM * ROWB + 2 * TN * ROWB)  // 61440
#define NSTAGE  3
#define GSMEM   (NSTAGE * STAGE_B)   // 184320

// 256 threads: A) each thread owns one of 256 A-rows (4 cp16 hi + 4 lo);
//              B) 2 threads per B-row (2 cp16 hi + 2 lo each).
__device__ __forceinline__ void load_stage(
    uint32_t sbase, int buf,
    const __nv_bfloat16* Ah, const __nv_bfloat16* Al,
    const __nv_bfloat16* Bh, const __nv_bfloat16* Bl,
    int lda, int ldb, int kt, int tid)
{
    uint32_t st = sbase + buf * STAGE_B;
    // A: row = tid, 32 bf16 = 64B
    {
        uint32_t sa = st + tid * ROWB;
        size_t ga = (size_t)tid * lda + kt * 32;
#pragma unroll
        for (int u = 0; u < 4; u++) {
            cp16(sa + OFF_AH + u * 16, Ah + ga + u * 8);
            cp16(sa + OFF_AL + u * 16, Al + ga + u * 8);
        }
    }
    // B: row = tid>>1, half = tid&1 (16 bf16 = 32B)
    {
        int br = tid >> 1, bh2 = (tid & 1) * 16;
        uint32_t sb = st + br * ROWB + bh2 * 2;
        size_t gb = (size_t)br * ldb + kt * 32 + bh2;
#pragma unroll
        for (int u = 0; u < 2; u++) {
            cp16(sb + OFF_BH + u * 16, Bh + gb + u * 8);
            cp16(sb + OFF_BL + u * 16, Bl + gb + u * 8);
        }
    }
}

// acc[mt][nt][4]: mt 0..3 (16-row), nt 0..7 (8-col)
__device__ __forceinline__ void compute_stage(uint32_t sbase, int buf,
                                              int wm, int wn, int lane,
                                              float acc[4][8][4])
{
    uint32_t base = sbase + buf * STAGE_B;
    uint32_t rowoff = (lane & 15) * ROWB + (lane >> 4) * 16;
#pragma unroll
    for (int kk = 0; kk < 2; kk++) {
        uint32_t bhf[4][4], blf[4][4];
#pragma unroll
        for (int g = 0; g < 4; g++) {   // 4 n16 groups cover 64 cols
            uint32_t ba = base + (wn * 64 + g * 16) * ROWB + kk * 32 + rowoff;
            ldsm4(bhf[g], ba + OFF_BH);
            ldsm4(blf[g], ba + OFF_BL);
        }
#pragma unroll
        for (int mt = 0; mt < 4; mt++) {
            uint32_t ah[4], al[4];
            uint32_t aa = base + (wm * 64 + mt * 16) * ROWB + kk * 32 + rowoff;
            ldsm4(ah, aa + OFF_AH);
            ldsm4(al, aa + OFF_AL);
#pragma unroll
            for (int nt = 0; nt < 8; nt++) {
                uint32_t b0h = bhf[nt >> 1][nt & 1], b1h = bhf[nt >> 1][(nt & 1) + 2];
                uint32_t b0l = blf[nt >> 1][nt & 1], b1l = blf[nt >> 1][(nt & 1) + 2];
                mma16816(acc[mt][nt], ah, b0h, b1h);   // hi*hi
                mma16816(acc[mt][nt], ah, b0l, b1l);   // hi*lo
                mma16816(acc[mt][nt], al, b0h, b1h);   // lo*hi
            }
        }
    }
}

__device__ __forceinline__ void gemm_mainloop(
    uint32_t sbase,
    const __nv_bfloat16* Ah, const __nv_bfloat16* Al,
    const __nv_bfloat16* Bh, const __nv_bfloat16* Bl,
    int lda, int ldb, int nk, float acc[4][8][4])
{
    int tid = threadIdx.x, lane = tid & 31, wid = tid >> 5;
    int wm = wid & 3, wn = wid >> 2;

    load_stage(sbase, 0, Ah, Al, Bh, Bl, lda, ldb, 0, tid);
    CP_COMMIT();
    if (nk > 1) load_stage(sbase, 1, Ah, Al, Bh, Bl, lda, ldb, 1, tid);
    CP_COMMIT();

    int buf = 0, nbuf = 2;
#pragma unroll 1
    for (int kt = 0; kt < nk; kt++) {
        CP_WAIT(1);                 // stage kt resident
        __syncthreads();            // all warps done with buffer `nbuf`
        if (kt + 2 < nk)
            load_stage(sbase, nbuf, Ah, Al, Bh, Bl, lda, ldb, kt + 2, tid);
        CP_COMMIT();                // empty near the tail — keeps counts exact
        compute_stage(sbase, buf, wm, wn, lane, acc);
        buf = (buf == NSTAGE - 1) ? 0 : buf + 1;
        nbuf = (nbuf == NSTAGE - 1) ? 0 : nbuf + 1;
    }
}

// ---------------------------------------------------------------------------
// Kernel 1: LayerNorm -> bf16 hi/lo split output
// ---------------------------------------------------------------------------
__global__ void __launch_bounds__(256) ln_kernel(const float* __restrict__ x,
                                                 const float* __restrict__ lnw,
                                                 const float* __restrict__ lnb) {
    __shared__ float sred[16];
    int row = blockIdx.x;
    const float* xr = x + (size_t)row * EE;
    int t = threadIdx.x;

    float4 vv[4];
    float s = 0.f, ss = 0.f;
#pragma unroll
    for (int u = 0; u < 4; u++) {
        vv[u] = *(const float4*)(xr + u * 1024 + t * 4);
        s  += vv[u].x + vv[u].y + vv[u].z + vv[u].w;
        ss += vv[u].x * vv[u].x + vv[u].y * vv[u].y
            + vv[u].z * vv[u].z + vv[u].w * vv[u].w;
    }
#pragma unroll
    for (int o = 16; o; o >>= 1) {
        s  += __shfl_xor_sync(0xffffffffu, s, o);
        ss += __shfl_xor_sync(0xffffffffu, ss, o);
    }
    if ((t & 31) == 0) { sred[t >> 5] = s; sred[8 + (t >> 5)] = ss; }
    __syncthreads();
    if (t < 8) {
        float a = sred[t], b = sred[8 + t];
#pragma unroll
        for (int o = 4; o; o >>= 1) {
            a += __shfl_xor_sync(0xffu, a, o);
            b += __shfl_xor_sync(0xffu, b, o);
        }
        if (t == 0) { sred[0] = a; sred[8] = b; }
    }
    __syncthreads();
    float mean = sred[0] * (1.0f / EE);
    float var  = sred[8] * (1.0f / EE) - mean * mean;
    float inv  = rsqrtf(var + 1e-5f);

#pragma unroll
    for (int u = 0; u < 4; u++) {
        float4 w = *(const float4*)(lnw + u * 1024 + t * 4);
        float4 b = *(const float4*)(lnb + u * 1024 + t * 4);
        float o0 = (vv[u].x - mean) * inv * w.x + b.x;
        float o1 = (vv[u].y - mean) * inv * w.y + b.y;
        float o2 = (vv[u].z - mean) * inv * w.z + b.z;
        float o3 = (vv[u].w - mean) * inv * w.w + b.w;
        uint32_t l0, l1;
        uint32_t h0 = pack_hilo(o0, o1, l0);
        uint32_t h1 = pack_hilo(o2, o3, l1);
        size_t idx = (size_t)row * EE + u * 1024 + t * 4;
        *(uint2*)(g_xh + idx) = make_uint2(h0, h1);
        *(uint2*)(g_xl + idx) = make_uint2(l0, l1);
    }
}

// ---------------------------------------------------------------------------
// Kernel 1b: fp32 -> bf16 hi/lo weight conversion (dst offset selects q/k)
// ---------------------------------------------------------------------------
__global__ void __launch_bounds__(256) cvt_kernel(const float* __restrict__ in,
                                                  size_t off) {
    size_t i = ((size_t)blockIdx.x * 256 + threadIdx.x) * 4;
    float4 v = *(const float4*)(in + i);
    uint32_t l0, l1;
    uint32_t h0 = pack_hilo(v.x, v.y, l0);
    uint32_t h1 = pack_hilo(v.z, v.w, l1);
    *(uint2*)(g_wh + off + i) = make_uint2(h0, h1);
    *(uint2*)(g_wl + off + i) = make_uint2(l0, l1);
}

// ---------------------------------------------------------------------------
// Kernel 2: fused Q+K projection GEMM (z dim selects head) + bias + RoPE
// + transposed store + bf16 hi/lo re-split for the scores GEMM.
// ---------------------------------------------------------------------------
__global__ void __launch_bounds__(256, 1) proj_mma(const float* __restrict__ qb,
                                                   const float* __restrict__ kb,
                                                   const float* __restrict__ ep,
                                                   const int* __restrict__ pid,
                                                   float* __restrict__ oq,
                                                   float* __restrict__ ok) {
    extern __shared__ char smem[];
    uint32_t sbase = smem_u32(smem);
    int sel = blockIdx.z;
    int bm = blockIdx.y * TM, bn = blockIdx.x * TN;

    float acc[4][8][4];
#pragma unroll
    for (int i = 0; i < 4; i++)
#pragma unroll
        for (int j = 0; j < 8; j++)
#pragma unroll
            for (int k = 0; k < 4; k++) acc[i][j][k] = 0.f;

    size_t woff = (size_t)sel * EE * EE + (size_t)bn * EE;
    gemm_mainloop(sbase,
                  g_xh + (size_t)bm * EE, g_xl + (size_t)bm * EE,
                  g_wh + woff, g_wl + woff,
                  EE, EE, EE / 32, acc);

    const float* bias = sel ? kb : qb;
    float* out = sel ? ok : oq;
    __nv_bfloat16* ohh = sel ? g_kh : g_qh;
    __nv_bfloat16* oll = sel ? g_kl : g_ql;

    int tid = threadIdx.x, lane = tid & 31, wid = tid >> 5;
    int wm = wid & 3, wn = wid >> 2;

#pragma unroll
    for (int mt = 0; mt < 4; mt++)
#pragma unroll
        for (int half = 0; half < 2; half++) {
            int row = bm + wm * 64 + mt * 16 + (lane >> 2) + half * 8;
            int bb = row >> 11, s = row & (SS - 1);
            int pos = pid[row];
            const float* epp = ep + (size_t)pos * RR;
#pragma unroll
            for (int nt = 0; nt < 8; nt++) {
                int c = bn + wn * 64 + nt * 8 + (lane & 3) * 2;
                float2 bv = *(const float2*)(bias + c);
                float v0 = acc[mt][nt][half * 2 + 0] + bv.x;
                float v1 = acc[mt][nt][half * 2 + 1] + bv.y;
                int h = c >> 8, d = c & 255;
                if (d < RR) {
                    int j = d >> 1;
                    float sv = epp[j], cv = epp[32 + j];
                    float t0 = v0, t1 = v1;
                    v0 = t0 * cv - t1 * sv;
                    v1 = t1 * cv + t0 * sv;
                }
                size_t o = (((size_t)(bb * HH + h)) * SS + s) * DD + d;
                *(float2*)(out + o) = make_float2(v0, v1);
                uint32_t lo, hi = pack_hilo(v0, v1, lo);
                *(uint32_t*)(ohh + o) = hi;
                *(uint32_t*)(oll + o) = lo;
            }
        }
}

// ---------------------------------------------------------------------------
// Kernel 3: causal scores GEMM, tiles 256x128, K=256.
// ---------------------------------------------------------------------------
__global__ void __launch_bounds__(256, 1) scores_mma(float* __restrict__ attn) {
    int bm = blockIdx.y * TM, bn = blockIdx.x * TN;
    if (bn > bm + TM - 1) return;     // fully masked tile
    extern __shared__ char smem[];
    uint32_t sbase = smem_u32(smem);
    int bh = blockIdx.z;

    float acc[4][8][4];
#pragma unroll
    for (int i = 0; i < 4; i++)
#pragma unroll
        for (int j = 0; j < 8; j++)
#pragma unroll
            for (int k = 0; k < 4; k++) acc[i][j][k] = 0.f;

    size_t qb = (size_t)bh * SS * DD + (size_t)bm * DD;
    size_t kb = (size_t)bh * SS * DD + (size_t)bn * DD;
    gemm_mainloop(sbase, g_qh + qb, g_ql + qb, g_kh + kb, g_kl + kb,
                  DD, DD, DD / 32, acc);

    int tid = threadIdx.x, lane = tid & 31, wid = tid >> 5;
    int wm = wid & 3, wn = wid >> 2;
    float* C = attn + (size_t)bh * SS * SS;

#pragma unroll
    for (int mt = 0; mt < 4; mt++)
#pragma unroll
        for (int half = 0; half < 2; half++) {
            int row = bm + wm * 64 + mt * 16 + (lane >> 2) + half * 8;
#pragma unroll
            for (int nt = 0; nt < 8; nt++) {
                int c = bn + wn * 64 + nt * 8 + (lane & 3) * 2;
                *(float2*)(C + (size_t)row * SS + c) = make_float2(
                    acc[mt][nt][half * 2 + 0] * 0.0625f,
                    acc[mt][nt][half * 2 + 1] * 0.0625f);
            }
        }
}

// ---------------------------------------------------------------------------
// Kernel 4: in-place causal softmax
// ---------------------------------------------------------------------------
__global__ void __launch_bounds__(256) softmax_kernel(float* __restrict__ attn) {
    __shared__ float sred[8];
    int r = blockIdx.x;
    int i = r & (SS - 1);
    float* p = attn + (size_t)r * SS;
    int valid = i + 1;
    int t = threadIdx.x;

    float v[8];
    float mx = NEG_INF;
#pragma unroll
    for (int u = 0; u < 8; u++) {
        int j = t + u * 256;
        v[u] = (j < valid) ? p[j] : NEG_INF;
        mx = fmaxf(mx, v[u]);
    }
#pragma unroll
    for (int o = 16; o; o >>= 1) mx = fmaxf(mx, __shfl_xor_sync(0xffffffffu, mx, o));
    if ((t & 31) == 0) sred[t >> 5] = mx;
    __syncthreads();
    if (t < 8) {
        float m2 = sred[t];
#pragma unroll
        for (int o = 4; o; o >>= 1) m2 = fmaxf(m2, __shfl_xor_sync(0xffu, m2, o));
        if (t == 0) sred[0] = m2;
    }
    __syncthreads();
    mx = sred[0];

    float sum = 0.f;
#pragma unroll
    for (int u = 0; u < 8; u++) {
        int j = t + u * 256;
        if (j < valid) { v[u] = expf(v[u] - mx); sum += v[u]; }
    }
#pragma unroll
    for (int o = 16; o; o >>= 1) sum += __shfl_xor_sync(0xffffffffu, sum, o);
    __syncthreads();
    if ((t & 31) == 0) sred[t >> 5] = sum;
    __syncthreads();
    if (t < 8) {
        float s2 = sred[t];
#pragma unroll
        for (int o = 4; o; o >>= 1) s2 += __shfl_xor_sync(0xffu, s2, o);
        if (t == 0) sred[0] = s2;
    }
    __syncthreads();
    float inv = 1.0f / sred[0];

#pragma unroll
    for (int u = 0; u < 8; u++) {
        int j = t + u * 256;
        p[j] = (j < valid) ? v[u] * inv : 0.f;
    }
}

// ---------------------------------------------------------------------------
// Launch
// ---------------------------------------------------------------------------
extern "C" void kernel_launch(void* const* d_in, const int* in_sizes, int n_in,
                              void* d_out, int out_size) {
    const float* x   = (const float*)d_in[0];
    const float* qw  = (const float*)d_in[1];
    const float* qb  = (const float*)d_in[2];
    const float* kw  = (const float*)d_in[3];
    const float* kb  = (const float*)d_in[4];
    const float* lnw = (const float*)d_in[5];
    const float* lnb = (const float*)d_in[6];
    const float* ep  = (const float*)d_in[7];
    const int*   pid = (const int*)d_in[8];

    float* oq = (float*)d_out;
    float* ok = oq + (size_t)BB * HH * SS * DD;
    float* oa = ok + (size_t)BB * HH * SS * DD;

    cudaFuncSetAttribute(proj_mma,   cudaFuncAttributeMaxDynamicSharedMemorySize, GSMEM);
    cudaFuncSetAttribute(scores_mma, cudaFuncAttributeMaxDynamicSharedMemorySize, GSMEM);

    ln_kernel<<<NTOK, 256>>>(x, lnw, lnb);
    cvt_kernel<<<(int)((size_t)EE * EE / 1024), 256>>>(qw, 0);
    cvt_kernel<<<(int)((size_t)EE * EE / 1024), 256>>>(kw, (size_t)EE * EE);

    dim3 gproj(EE / TN, NTOK / TM, 2);
    proj_mma<<<gproj, 256, GSMEM>>>(qb, kb, ep, pid, oq, ok);

    dim3 gsc(SS / TN, SS / TM, BB * HH);
    scores_mma<<<gsc, 256, GSMEM>>>(oa);

    softmax_kernel<<<BB * HH * SS, 256>>>(oa);
}

// round 15
// speedup vs baseline: 2.2771x; 1.1422x over previous
// v2 resubmission — semantically identical to R11/R12 submission; comment-only
// delta to alter the source hash after two consecutive container failures.
#include <cuda_runtime.h>
#include <cuda_bf16.h>
#include <stdint.h>

// Problem constants
#define BB   2
#define SS   2048
#define EE   4096
#define HH   16
#define DD   256
#define RR   64
#define NTOK (BB * SS)
#define NEG_INF (-3.402823466e38f)

// ---------------------------------------------------------------------------
// Static device scratch (no allocation allowed)
// ---------------------------------------------------------------------------
__device__ __nv_bfloat16 g_xh[(size_t)NTOK * EE];        // xnorm hi
__device__ __nv_bfloat16 g_xl[(size_t)NTOK * EE];        // xnorm lo
__device__ __nv_bfloat16 g_wh[2 * (size_t)EE * EE];      // q|k weight hi
__device__ __nv_bfloat16 g_wl[2 * (size_t)EE * EE];      // q|k weight lo
__device__ __nv_bfloat16 g_qh[(size_t)BB * HH * SS * DD];
__device__ __nv_bfloat16 g_ql[(size_t)BB * HH * SS * DD];
__device__ __nv_bfloat16 g_kh[(size_t)BB * HH * SS * DD];
__device__ __nv_bfloat16 g_kl[(size_t)BB * HH * SS * DD];

// ---------------------------------------------------------------------------
// PTX helpers (sm_80-baseline only)
// ---------------------------------------------------------------------------
__device__ __forceinline__ uint32_t smem_u32(const void* p) {
    uint32_t a;
    asm("{ .reg .u64 t; cvta.to.shared.u64 t, %1; cvt.u32.u64 %0, t; }"
        : "=r"(a) : "l"(p));
    return a;
}
__device__ __forceinline__ void ldsm4(uint32_t* r, uint32_t addr) {
    asm volatile("ldmatrix.sync.aligned.m8n8.x4.shared.b16 {%0,%1,%2,%3}, [%4];"
                 : "=r"(r[0]), "=r"(r[1]), "=r"(r[2]), "=r"(r[3]) : "r"(addr));
}
__device__ __forceinline__ void mma16816(float* c, const uint32_t* a,
                                         uint32_t b0, uint32_t b1) {
    asm volatile("mma.sync.aligned.m16n8k16.row.col.f32.bf16.bf16.f32 "
                 "{%0,%1,%2,%3}, {%4,%5,%6,%7}, {%8,%9}, {%0,%1,%2,%3};"
                 : "+f"(c[0]), "+f"(c[1]), "+f"(c[2]), "+f"(c[3])
                 : "r"(a[0]), "r"(a[1]), "r"(a[2]), "r"(a[3]), "r"(b0), "r"(b1));
}
__device__ __forceinline__ void cp16(uint32_t s, const void* g) {
    asm volatile("cp.async.cg.shared.global [%0], [%1], 16;"
                 :: "r"(s), "l"(__cvta_generic_to_global(g)));
}
#define CP_COMMIT() asm volatile("cp.async.commit_group;")
#define CP_WAIT(N)  asm volatile("cp.async.wait_group %0;" :: "n"(N))

__device__ __forceinline__ uint32_t pack_hilo(float a, float b, uint32_t& lo) {
    __nv_bfloat16 ha = __float2bfloat16_rn(a), hb = __float2bfloat16_rn(b);
    __nv_bfloat16 la = __float2bfloat16_rn(a - __bfloat162float(ha));
    __nv_bfloat16 lb = __float2bfloat16_rn(b - __bfloat162float(hb));
    lo = (uint32_t)__bfloat16_as_ushort(la) | ((uint32_t)__bfloat16_as_ushort(lb) << 16);
    return (uint32_t)__bfloat16_as_ushort(ha) | ((uint32_t)__bfloat16_as_ushort(hb) << 16);
}

// ---------------------------------------------------------------------------
// GEMM machinery: CTA tile 128x128, BK=32, 8 warps, warp tile 64x32,
// bf16x3 split, 2-stage double buffer, ONE __syncthreads per stage,
// 2 CTAs per SM (smem 80KB, regs capped at 128 via launch_bounds).
// Smem stage: 4 tiles (Ahi,Alo,Bhi,Blo) of 128 rows x 40 bf16 (80B rows).
// ---------------------------------------------------------------------------
#define KPAD    40
#define ROWB    80
#define TILE_B  (128 * ROWB)         // 10240 bytes per tile
#define STAGE_B (4 * TILE_B)         // 40960
#define GSMEM   (2 * STAGE_B)        // 81920

__device__ __forceinline__ void load_stage(
    uint32_t sbase, int buf,
    const __nv_bfloat16* Ah, const __nv_bfloat16* Al,
    const __nv_bfloat16* Bh, const __nv_bfloat16* Bl,
    int lda, int kt, int lrow, int lch)
{
    uint32_t st = sbase + buf * STAGE_B + lrow * ROWB + lch * 16;
    size_t go = (size_t)lrow * lda + kt * 32 + lch * 8;
    cp16(st,                   Ah + go);
    cp16(st + 16,              Ah + go + 8);
    cp16(st + TILE_B,          Al + go);
    cp16(st + TILE_B + 16,     Al + go + 8);
    cp16(st + 2 * TILE_B,      Bh + go);
    cp16(st + 2 * TILE_B + 16, Bh + go + 8);
    cp16(st + 3 * TILE_B,      Bl + go);
    cp16(st + 3 * TILE_B + 16, Bl + go + 8);
}

__device__ __forceinline__ void compute_stage(uint32_t sbase, int buf,
                                              int wm, int wn, int lane,
                                              float acc[4][4][4])
{
    uint32_t base = sbase + buf * STAGE_B;
    uint32_t rowoff = (lane & 15) * ROWB + (lane >> 4) * 16;
#pragma unroll
    for (int kk = 0; kk < 2; kk++) {
        uint32_t bh[2][4], bl[2][4];
#pragma unroll
        for (int nt2 = 0; nt2 < 2; nt2++) {
            uint32_t ba = base + 2 * TILE_B + (wn * 32 + nt2 * 16) * ROWB + kk * 32 + rowoff;
            ldsm4(bh[nt2], ba);
            ldsm4(bl[nt2], ba + TILE_B);
        }
#pragma unroll
        for (int mt = 0; mt < 4; mt++) {
            uint32_t ah[4], al[4];
            uint32_t aa = base + (wm * 64 + mt * 16) * ROWB + kk * 32 + rowoff;
            ldsm4(ah, aa);
            ldsm4(al, aa + TILE_B);
#pragma unroll
            for (int nt = 0; nt < 4; nt++) {
                uint32_t b0h = bh[nt >> 1][nt & 1], b1h = bh[nt >> 1][(nt & 1) + 2];
                uint32_t b0l = bl[nt >> 1][nt & 1], b1l = bl[nt >> 1][(nt & 1) + 2];
                mma16816(acc[mt][nt], ah, b0h, b1h);   // hi*hi
                mma16816(acc[mt][nt], ah, b0l, b1l);   // hi*lo
                mma16816(acc[mt][nt], al, b0h, b1h);   // lo*hi
            }
        }
    }
}

// 2-stage, one __syncthreads per iteration. At iteration kt:
//   wait(0): stage kt's loads landed (committed last iteration).
//   sync:    every warp finished compute(kt-1), which used buffer (kt+1)&1.
//   prefetch kt+1 into (kt+1)&1, overlapping compute(kt).
__device__ __forceinline__ void gemm_mainloop(
    uint32_t sbase,
    const __nv_bfloat16* Ah, const __nv_bfloat16* Al,
    const __nv_bfloat16* Bh, const __nv_bfloat16* Bl,
    int lda, int nk, float acc[4][4][4])
{
    int tid = threadIdx.x, lane = tid & 31, wid = tid >> 5;
    int wm = wid & 1, wn = wid >> 1;
    int lrow = tid >> 1, lch = (tid & 1) * 2;

    load_stage(sbase, 0, Ah, Al, Bh, Bl, lda, 0, lrow, lch);
    CP_COMMIT();

#pragma unroll 1
    for (int kt = 0; kt < nk; kt++) {
        CP_WAIT(0);
        __syncthreads();
        if (kt + 1 < nk) {
            load_stage(sbase, (kt + 1) & 1, Ah, Al, Bh, Bl, lda, kt + 1, lrow, lch);
            CP_COMMIT();
        }
        compute_stage(sbase, kt & 1, wm, wn, lane, acc);
    }
}

// ---------------------------------------------------------------------------
// Kernel 1: LayerNorm -> bf16 hi/lo split output
// ---------------------------------------------------------------------------
__global__ void __launch_bounds__(256) ln_kernel(const float* __restrict__ x,
                                                 const float* __restrict__ lnw,
                                                 const float* __restrict__ lnb) {
    __shared__ float sred[16];
    int row = blockIdx.x;
    const float* xr = x + (size_t)row * EE;
    int t = threadIdx.x;

    float4 vv[4];
    float s = 0.f, ss = 0.f;
#pragma unroll
    for (int u = 0; u < 4; u++) {
        vv[u] = *(const float4*)(xr + u * 1024 + t * 4);
        s  += vv[u].x + vv[u].y + vv[u].z + vv[u].w;
        ss += vv[u].x * vv[u].x + vv[u].y * vv[u].y
            + vv[u].z * vv[u].z + vv[u].w * vv[u].w;
    }
#pragma unroll
    for (int o = 16; o; o >>= 1) {
        s  += __shfl_xor_sync(0xffffffffu, s, o);
        ss += __shfl_xor_sync(0xffffffffu, ss, o);
    }
    if ((t & 31) == 0) { sred[t >> 5] = s; sred[8 + (t >> 5)] = ss; }
    __syncthreads();
    if (t < 8) {
        float a = sred[t], b = sred[8 + t];
#pragma unroll
        for (int o = 4; o; o >>= 1) {
            a += __shfl_xor_sync(0xffu, a, o);
            b += __shfl_xor_sync(0xffu, b, o);
        }
        if (t == 0) { sred[0] = a; sred[8] = b; }
    }
    __syncthreads();
    float mean = sred[0] * (1.0f / EE);
    float var  = sred[8] * (1.0f / EE) - mean * mean;
    float inv  = rsqrtf(var + 1e-5f);

#pragma unroll
    for (int u = 0; u < 4; u++) {
        float4 w = *(const float4*)(lnw + u * 1024 + t * 4);
        float4 b = *(const float4*)(lnb + u * 1024 + t * 4);
        float o0 = (vv[u].x - mean) * inv * w.x + b.x;
        float o1 = (vv[u].y - mean) * inv * w.y + b.y;
        float o2 = (vv[u].z - mean) * inv * w.z + b.z;
        float o3 = (vv[u].w - mean) * inv * w.w + b.w;
        uint32_t l0, l1;
        uint32_t h0 = pack_hilo(o0, o1, l0);
        uint32_t h1 = pack_hilo(o2, o3, l1);
        size_t idx = (size_t)row * EE + u * 1024 + t * 4;
        *(uint2*)(g_xh + idx) = make_uint2(h0, h1);
        *(uint2*)(g_xl + idx) = make_uint2(l0, l1);
    }
}

// ---------------------------------------------------------------------------
// Kernel 1b: fp32 -> bf16 hi/lo weight conversion (dst offset selects q/k)
// ---------------------------------------------------------------------------
__global__ void __launch_bounds__(256) cvt_kernel(const float* __restrict__ in,
                                                  size_t off) {
    size_t i = ((size_t)blockIdx.x * 256 + threadIdx.x) * 4;
    float4 v = *(const float4*)(in + i);
    uint32_t l0, l1;
    uint32_t h0 = pack_hilo(v.x, v.y, l0);
    uint32_t h1 = pack_hilo(v.z, v.w, l1);
    *(uint2*)(g_wh + off + i) = make_uint2(h0, h1);
    *(uint2*)(g_wl + off + i) = make_uint2(l0, l1);
}

// ---------------------------------------------------------------------------
// Kernel 2: fused Q+K projection GEMM (z selects Q/K) + bias + RoPE
// + transposed store + bf16 hi/lo re-split for the scores GEMM.
// ---------------------------------------------------------------------------
__global__ void __launch_bounds__(256, 2) proj_mma(const float* __restrict__ qb,
                                                   const float* __restrict__ kb,
                                                   const float* __restrict__ ep,
                                                   const int* __restrict__ pid,
                                                   float* __restrict__ oq,
                                                   float* __restrict__ ok) {
    extern __shared__ char smem[];
    uint32_t sbase = smem_u32(smem);
    int sel = blockIdx.z;
    int bm = blockIdx.y * 128, bn = blockIdx.x * 128;

    float acc[4][4][4];
#pragma unroll
    for (int i = 0; i < 4; i++)
#pragma unroll
        for (int j = 0; j < 4; j++)
#pragma unroll
            for (int k = 0; k < 4; k++) acc[i][j][k] = 0.f;

    size_t woff = (size_t)sel * EE * EE + (size_t)bn * EE;
    gemm_mainloop(sbase,
                  g_xh + (size_t)bm * EE, g_xl + (size_t)bm * EE,
                  g_wh + woff, g_wl + woff,
                  EE, EE / 32, acc);

    const float* bias = sel ? kb : qb;
    float* out = sel ? ok : oq;
    __nv_bfloat16* ohh = sel ? g_kh : g_qh;
    __nv_bfloat16* oll = sel ? g_kl : g_ql;

    int tid = threadIdx.x, lane = tid & 31, wid = tid >> 5;
    int wm = wid & 1, wn = wid >> 1;

#pragma unroll
    for (int mt = 0; mt < 4; mt++)
#pragma unroll
        for (int half = 0; half < 2; half++) {
            int row = bm + wm * 64 + mt * 16 + (lane >> 2) + half * 8;
            int bb = row >> 11, s = row & (SS - 1);
            int pos = pid[row];
            const float* epp = ep + (size_t)pos * RR;
#pragma unroll
            for (int nt = 0; nt < 4; nt++) {
                int c = bn + wn * 32 + nt * 8 + (lane & 3) * 2;
                float2 bv = *(const float2*)(bias + c);
                float v0 = acc[mt][nt][half * 2 + 0] + bv.x;
                float v1 = acc[mt][nt][half * 2 + 1] + bv.y;
                int h = c >> 8, d = c & 255;
                if (d < RR) {
                    int j = d >> 1;
                    float sv = epp[j], cv = epp[32 + j];
                    float t0 = v0, t1 = v1;
                    v0 = t0 * cv - t1 * sv;
                    v1 = t1 * cv + t0 * sv;
                }
                size_t o = (((size_t)(bb * HH + h)) * SS + s) * DD + d;
                *(float2*)(out + o) = make_float2(v0, v1);
                uint32_t lo, hi = pack_hilo(v0, v1, lo);
                *(uint32_t*)(ohh + o) = hi;
                *(uint32_t*)(oll + o) = lo;
            }
        }
}

// ---------------------------------------------------------------------------
// Kernel 3: causal scores GEMM, tiles 128x128, K=256.
// ---------------------------------------------------------------------------
__global__ void __launch_bounds__(256, 2) scores_mma(float* __restrict__ attn) {
    if (blockIdx.x > blockIdx.y) return;   // fully masked tile
    extern __shared__ char smem[];
    uint32_t sbase = smem_u32(smem);
    int bh = blockIdx.z;
    int bm = blockIdx.y * 128, bn = blockIdx.x * 128;

    float acc[4][4][4];
#pragma unroll
    for (int i = 0; i < 4; i++)
#pragma unroll
        for (int j = 0; j < 4; j++)
#pragma unroll
            for (int k = 0; k < 4; k++) acc[i][j][k] = 0.f;

    size_t qb = (size_t)bh * SS * DD + (size_t)bm * DD;
    size_t kb = (size_t)bh * SS * DD + (size_t)bn * DD;
    gemm_mainloop(sbase, g_qh + qb, g_ql + qb, g_kh + kb, g_kl + kb,
                  DD, DD / 32, acc);

    int tid = threadIdx.x, lane = tid & 31, wid = tid >> 5;
    int wm = wid & 1, wn = wid >> 1;
    float* C = attn + (size_t)bh * SS * SS;

#pragma unroll
    for (int mt = 0; mt < 4; mt++)
#pragma unroll
        for (int half = 0; half < 2; half++) {
            int row = bm + wm * 64 + mt * 16 + (lane >> 2) + half * 8;
#pragma unroll
            for (int nt = 0; nt < 4; nt++) {
                int c = bn + wn * 32 + nt * 8 + (lane & 3) * 2;
                *(float2*)(C + (size_t)row * SS + c) = make_float2(
                    acc[mt][nt][half * 2 + 0] * 0.0625f,
                    acc[mt][nt][half * 2 + 1] * 0.0625f);
            }
        }
}

// ---------------------------------------------------------------------------
// Kernel 4: in-place causal softmax
// ---------------------------------------------------------------------------
__global__ void __launch_bounds__(256) softmax_kernel(float* __restrict__ attn) {
    __shared__ float sred[8];
    int r = blockIdx.x;
    int i = r & (SS - 1);
    float* p = attn + (size_t)r * SS;
    int valid = i + 1;
    int t = threadIdx.x;

    float v[8];
    float mx = NEG_INF;
#pragma unroll
    for (int u = 0; u < 8; u++) {
        int j = t + u * 256;
        v[u] = (j < valid) ? p[j] : NEG_INF;
        mx = fmaxf(mx, v[u]);
    }
#pragma unroll
    for (int o = 16; o; o >>= 1) mx = fmaxf(mx, __shfl_xor_sync(0xffffffffu, mx, o));
    if ((t & 31) == 0) sred[t >> 5] = mx;
    __syncthreads();
    if (t < 8) {
        float m2 = sred[t];
#pragma unroll
        for (int o = 4; o; o >>= 1) m2 = fmaxf(m2, __shfl_xor_sync(0xffu, m2, o));
        if (t == 0) sred[0] = m2;
    }
    __syncthreads();
    mx = sred[0];

    float sum = 0.f;
#pragma unroll
    for (int u = 0; u < 8; u++) {
        int j = t + u * 256;
        if (j < valid) { v[u] = expf(v[u] - mx); sum += v[u]; }
    }
#pragma unroll
    for (int o = 16; o; o >>= 1) sum += __shfl_xor_sync(0xffffffffu, sum, o);
    __syncthreads();
    if ((t & 31) == 0) sred[t >> 5] = sum;
    __syncthreads();
    if (t < 8) {
        float s2 = sred[t];
#pragma unroll
        for (int o = 4; o; o >>= 1) s2 += __shfl_xor_sync(0xffu, s2, o);
        if (t == 0) sred[0] = s2;
    }
    __syncthreads();
    float inv = 1.0f / sred[0];

#pragma unroll
    for (int u = 0; u < 8; u++) {
        int j = t + u * 256;
        p[j] = (j < valid) ? v[u] * inv : 0.f;
    }
}

// ---------------------------------------------------------------------------
// Launch
// ---------------------------------------------------------------------------
extern "C" void kernel_launch(void* const* d_in, const int* in_sizes, int n_in,
                              void* d_out, int out_size) {
    const float* x   = (const float*)d_in[0];
    const float* qw  = (const float*)d_in[1];
    const float* qb  = (const float*)d_in[2];
    const float* kw  = (const float*)d_in[3];
    const float* kb  = (const float*)d_in[4];
    const float* lnw = (const float*)d_in[5];
    const float* lnb = (const float*)d_in[6];
    const float* ep  = (const float*)d_in[7];
    const int*   pid = (const int*)d_in[8];

    float* oq = (float*)d_out;
    float* ok = oq + (size_t)BB * HH * SS * DD;
    float* oa = ok + (size_t)BB * HH * SS * DD;

    cudaFuncSetAttribute(proj_mma,   cudaFuncAttributeMaxDynamicSharedMemorySize, GSMEM);
    cudaFuncSetAttribute(scores_mma, cudaFuncAttributeMaxDynamicSharedMemorySize, GSMEM);

    ln_kernel<<<NTOK, 256>>>(x, lnw, lnb);
    cvt_kernel<<<(int)((size_t)EE * EE / 1024), 256>>>(qw, 0);
    cvt_kernel<<<(int)((size_t)EE * EE / 1024), 256>>>(kw, (size_t)EE * EE);

    dim3 gproj(EE / 128, NTOK / 128, 2);
    proj_mma<<<gproj, 256, GSMEM>>>(qb, kb, ep, pid, oq, ok);

    dim3 gsc(SS / 128, SS / 128, BB * HH);
    scores_mma<<<gsc, 256, GSMEM>>>(oa);

    softmax_kernel<<<BB * HH * SS, 256>>>(oa);
}